// round 5
// baseline (speedup 1.0000x reference)
#include <cuda_runtime.h>
#include <cuda_bf16.h>
#include <cstdint>

// HGAN triplet loss:
//   score[b] = b_fc + sum_k num_k/den_k       (b_att cancels in softmax,
//   num_k = sum_{n,m} exp(S_k[n,m])*F_k[n,m],  b_fc cancels in score diff)
//   S_k[n,m] = sum_h W_att[k,h]*Aa[h,n]*Ac[h,m]
//   F_k[n,m] = sum_h W_fc [k,h]*Aa[h,n]*Ac[h,m]
// Score GEMMs run on HMMA (mma.sync m16n8k16 bf16, fp32 acc) with hi/lo bf16
// splitting (3 passes) for fp32-class accuracy. tcgen05 is unavailable at the
// harness's compute_103 PTX target; mma.sync is baseline ISA.

#define B_ 32
#define N_ 256
#define E_ 300
#define H_ 256
#define K_ 8

// ---------------------------------------------------------------------------
// Device scratch (allocation-free per harness rules)
// ---------------------------------------------------------------------------
__device__ float    g_projT[3][B_][N_][H_];          // transposed: [n][h], 24 MB
__device__ uint32_t g_Cpk[B_][2][2][256][128];       // [b][side][hi/lo][m][h/2], 16 MB
__device__ float    g_num[2][B_][K_];
__device__ float    g_den[2][B_][K_];

// ---------------------------------------------------------------------------
// Helpers
// ---------------------------------------------------------------------------
__device__ __forceinline__ uint32_t smem_u32(const void* p) {
    uint32_t a;
    asm("{ .reg .u64 t; cvta.to.shared.u64 t, %1; cvt.u32.u64 %0, t; }" : "=r"(a) : "l"(p));
    return a;
}
// pack (v0 -> low half, v1 -> high half) as bf16x2
__device__ __forceinline__ uint32_t cvt2(float v0, float v1) {
    uint32_t r;
    asm("cvt.rn.bf16x2.f32 %0, %1, %2;" : "=r"(r) : "f"(v1), "f"(v0));
    return r;
}
// hi/lo bf16 split of a pair of fp32 values
__device__ __forceinline__ void split2(float v0, float v1, uint32_t& uhi, uint32_t& ulo) {
    uhi = cvt2(v0, v1);
    float f0 = __uint_as_float(uhi << 16);
    float f1 = __uint_as_float(uhi & 0xffff0000u);
    ulo = cvt2(v0 - f0, v1 - f1);
}
__device__ __forceinline__ void ldsm4(uint32_t* r, uint32_t addr) {
    asm volatile("ldmatrix.sync.aligned.m8n8.x4.shared.b16 {%0,%1,%2,%3}, [%4];"
        : "=r"(r[0]), "=r"(r[1]), "=r"(r[2]), "=r"(r[3]) : "r"(addr));
}
__device__ __forceinline__ void mma_bf16(float* d, const uint32_t* a,
                                         uint32_t b0, uint32_t b1) {
    asm volatile("mma.sync.aligned.m16n8k16.row.col.f32.bf16.bf16.f32 "
        "{%0,%1,%2,%3}, {%4,%5,%6,%7}, {%8,%9}, {%0,%1,%2,%3};"
        : "+f"(d[0]), "+f"(d[1]), "+f"(d[2]), "+f"(d[3])
        : "r"(a[0]), "r"(a[1]), "r"(a[2]), "r"(a[3]), "r"(b0), "r"(b1));
}

// ---------------------------------------------------------------------------
// Projection: g_projT[which][b][n][h] = bias[h] + sum_e X[b][n][e]*W[h][e]
// (R1 kernel, output transposed to [n][h] so score fills need no transpose)
// ---------------------------------------------------------------------------
__global__ __launch_bounds__(256)
void proj_kernel(const float* __restrict__ X, const float* __restrict__ W,
                 const float* __restrict__ bias, int which) {
    const int b  = blockIdx.z;
    const int h0 = blockIdx.y * 64;
    const int n0 = blockIdx.x * 64;
    const int tid = threadIdx.x;
    const int tx = tid & 15, ty = tid >> 4;

    __shared__ float Ws[20][68];
    __shared__ float Xs[20][68];

    float acc[4][4] = {};
    const float* Xb = X + (size_t)b * N_ * E_;

    for (int e0 = 0; e0 < E_; e0 += 20) {
        #pragma unroll
        for (int l = 0; l < 5; l++) {
            int idx = tid + l * 256;
            int rl = idx / 20;
            int el = idx - rl * 20;
            Ws[el][rl] = W [(h0 + rl) * E_ + e0 + el];
            Xs[el][rl] = Xb[(n0 + rl) * E_ + e0 + el];
        }
        __syncthreads();
        #pragma unroll
        for (int e = 0; e < 20; e++) {
            float4 wv4 = *(const float4*)&Ws[e][ty * 4];
            float4 xv4 = *(const float4*)&Xs[e][tx * 4];
            float wv[4] = {wv4.x, wv4.y, wv4.z, wv4.w};
            float xv[4] = {xv4.x, xv4.y, xv4.z, xv4.w};
            #pragma unroll
            for (int i = 0; i < 4; i++)
                #pragma unroll
                for (int j = 0; j < 4; j++)
                    acc[i][j] = fmaf(wv[i], xv[j], acc[i][j]);
        }
        __syncthreads();
    }

    float bb0 = bias[h0 + ty * 4 + 0];
    float bb1 = bias[h0 + ty * 4 + 1];
    float bb2 = bias[h0 + ty * 4 + 2];
    float bb3 = bias[h0 + ty * 4 + 3];
    #pragma unroll
    for (int j = 0; j < 4; j++) {
        int n = n0 + tx * 4 + j;
        float4 o = make_float4(acc[0][j] + bb0, acc[1][j] + bb1,
                               acc[2][j] + bb2, acc[3][j] + bb3);
        *(float4*)&g_projT[which][b][n][h0 + ty * 4] = o;
    }
}

// ---------------------------------------------------------------------------
// C-pack: hi/lo bf16 split of Ac (k-independent), layout [m][h] packed pairs.
// ---------------------------------------------------------------------------
__global__ __launch_bounds__(256)
void cpack_kernel() {
    const int b = blockIdx.x, side = blockIdx.y;
    const float* src = &g_projT[1 + side][b][0][0];
    for (int p = threadIdx.x; p < 256 * 128; p += 256) {
        int m = p >> 7, hp = p & 127;
        float2 v = *(const float2*)(src + m * H_ + hp * 2);
        uint32_t hi, lo;
        split2(v.x, v.y, hi, lo);
        g_Cpk[b][side][0][m][hp] = hi;
        g_Cpk[b][side][1][m][hp] = lo;
    }
}

// ---------------------------------------------------------------------------
// Score: CTA per (k, b, side). Output tiles 64n x 128m; h streamed in chunks
// of 32. A operand scaled by watt/wfc and hi/lo-split in-kernel; C operand
// copied from the global pack. Warp w: n-rows 16*(w&3), m-cols 64*(w>>2).
// Per k16 step / m32 half: 24 HMMA (S: hi*hi+lo*hi+hi*lo, F: same).
// ---------------------------------------------------------------------------
#define ASTR 20   // u32 stride per smem row (40 bf16 = 80 B, conflict-free)

__global__ __launch_bounds__(256, 2)
void score_kernel(const float* __restrict__ W_att, const float* __restrict__ W_fc) {
    __shared__ float watt_s[H_], wfc_s[H_];
    __shared__ uint32_t AShi[64 * ASTR], ASlo[64 * ASTR];
    __shared__ uint32_t AFhi[64 * ASTR], AFlo[64 * ASTR];
    __shared__ uint32_t Chi [128 * ASTR], Clo[128 * ASTR];
    __shared__ float rn[8], rd[8];

    const int tid  = threadIdx.x;
    const int lane = tid & 31, w = tid >> 5;
    const int k = blockIdx.x, b = blockIdx.y, side = blockIdx.z;

    for (int h = tid; h < H_; h += 256) {
        watt_s[h] = W_att[k * H_ + h];
        wfc_s[h]  = W_fc [k * H_ + h];
    }

    const float*    At = &g_projT[0][b][0][0];
    const uint32_t* Cp = &g_Cpk[b][side][0][0][0];

    const uint32_t aShb = smem_u32(AShi), aSlb = smem_u32(ASlo);
    const uint32_t aFhb = smem_u32(AFhi), aFlb = smem_u32(AFlo);
    const uint32_t cHb  = smem_u32(Chi),  cLb  = smem_u32(Clo);

    // fill-index precompute
    const int fa_n = tid >> 2, fa_i4 = (tid & 3) * 8;
    const int fc_var = tid >> 7, fc_m = tid & 127;
    uint32_t* fc_dst = (fc_var ? Clo : Chi) + fc_m * ASTR;

    // compute-index precompute
    const int wn0 = 16 * (w & 3), wm0 = 64 * (w >> 2);
    const uint32_t a_off = ((uint32_t)(wn0 + (lane & 15)) * ASTR * 4) + ((lane >> 4) << 4);
    const uint32_t c_row = (lane & 7) + ((lane >> 4) << 3);
    const uint32_t c_off = c_row * ASTR * 4 + (((lane >> 3) & 1) << 4);

    float num = 0.f, den = 0.f;

    for (int nt = 0; nt < 4; nt++) {
      for (int mt = 0; mt < 2; mt++) {
        float accS[2][4][4], accF[2][4][4];
        #pragma unroll
        for (int mh = 0; mh < 2; mh++)
            #pragma unroll
            for (int g = 0; g < 4; g++)
                #pragma unroll
                for (int r = 0; r < 4; r++) { accS[mh][g][r] = 0.f; accF[mh][g][r] = 0.f; }

        for (int hc = 0; hc < 8; hc++) {
            const int h0 = hc * 32;
            __syncthreads();   // previous chunk's compute done

            // ---- A fill: 64n x 32h, scaled + split (8 h-values per thread)
            {
                const float* src = At + (nt * 64 + fa_n) * H_ + h0 + fa_i4;
                float4 v0 = *(const float4*)src;
                float4 v1 = *(const float4*)(src + 4);
                float4 a0 = *(const float4*)(watt_s + h0 + fa_i4);
                float4 a1 = *(const float4*)(watt_s + h0 + fa_i4 + 4);
                float4 f0 = *(const float4*)(wfc_s  + h0 + fa_i4);
                float4 f1 = *(const float4*)(wfc_s  + h0 + fa_i4 + 4);
                const int bi = fa_n * ASTR + (fa_i4 >> 1);
                uint32_t hi, lo;
                split2(a0.x * v0.x, a0.y * v0.y, hi, lo); AShi[bi + 0] = hi; ASlo[bi + 0] = lo;
                split2(a0.z * v0.z, a0.w * v0.w, hi, lo); AShi[bi + 1] = hi; ASlo[bi + 1] = lo;
                split2(a1.x * v1.x, a1.y * v1.y, hi, lo); AShi[bi + 2] = hi; ASlo[bi + 2] = lo;
                split2(a1.z * v1.z, a1.w * v1.w, hi, lo); AShi[bi + 3] = hi; ASlo[bi + 3] = lo;
                split2(f0.x * v0.x, f0.y * v0.y, hi, lo); AFhi[bi + 0] = hi; AFlo[bi + 0] = lo;
                split2(f0.z * v0.z, f0.w * v0.w, hi, lo); AFhi[bi + 1] = hi; AFlo[bi + 1] = lo;
                split2(f1.x * v1.x, f1.y * v1.y, hi, lo); AFhi[bi + 2] = hi; AFlo[bi + 2] = lo;
                split2(f1.z * v1.z, f1.w * v1.w, hi, lo); AFhi[bi + 3] = hi; AFlo[bi + 3] = lo;
            }
            // ---- C fill: copy packed hi/lo rows (16 u32 per thread)
            {
                const uint32_t* s = Cp + (fc_var * 256 + mt * 128 + fc_m) * 128 + (h0 >> 1);
                uint4 q0 = *(const uint4*)(s + 0);
                uint4 q1 = *(const uint4*)(s + 4);
                uint4 q2 = *(const uint4*)(s + 8);
                uint4 q3 = *(const uint4*)(s + 12);
                *(uint4*)(fc_dst + 0)  = q0;
                *(uint4*)(fc_dst + 4)  = q1;
                *(uint4*)(fc_dst + 8)  = q2;
                *(uint4*)(fc_dst + 12) = q3;
            }
            __syncthreads();   // fill visible

            // ---- HMMA compute
            #pragma unroll
            for (int ks = 0; ks < 2; ks++) {
                const uint32_t hkb = (uint32_t)(ks * 32);   // 16 bf16 = 32 bytes
                uint32_t aSh[4], aSl[4], aFh[4], aFl[4];
                ldsm4(aSh, aShb + a_off + hkb);
                ldsm4(aSl, aSlb + a_off + hkb);
                ldsm4(aFh, aFhb + a_off + hkb);
                ldsm4(aFl, aFlb + a_off + hkb);
                #pragma unroll
                for (int mh = 0; mh < 2; mh++) {
                    const uint32_t mrow = (uint32_t)(wm0 + mh * 32) * ASTR * 4;
                    uint32_t c[8];
                    ldsm4(c + 0, cHb + mrow + c_off + hkb);
                    ldsm4(c + 4, cHb + mrow + 16 * ASTR * 4 + c_off + hkb);
                    #pragma unroll
                    for (int g = 0; g < 4; g++) {
                        mma_bf16(accS[mh][g], aSh, c[2*g], c[2*g+1]);
                        mma_bf16(accS[mh][g], aSl, c[2*g], c[2*g+1]);
                        mma_bf16(accF[mh][g], aFh, c[2*g], c[2*g+1]);
                        mma_bf16(accF[mh][g], aFl, c[2*g], c[2*g+1]);
                    }
                    ldsm4(c + 0, cLb + mrow + c_off + hkb);
                    ldsm4(c + 4, cLb + mrow + 16 * ASTR * 4 + c_off + hkb);
                    #pragma unroll
                    for (int g = 0; g < 4; g++) {
                        mma_bf16(accS[mh][g], aSh, c[2*g], c[2*g+1]);
                        mma_bf16(accF[mh][g], aFh, c[2*g], c[2*g+1]);
                    }
                }
            }
        }

        // ---- epilogue for this tile: exp + local reduce (logits O(0.2): safe)
        #pragma unroll
        for (int mh = 0; mh < 2; mh++)
            #pragma unroll
            for (int g = 0; g < 4; g++)
                #pragma unroll
                for (int r = 0; r < 4; r++) {
                    float e = __expf(accS[mh][g][r]);
                    den += e;
                    num = fmaf(e, accF[mh][g][r], num);
                }
      }
    }

    // block reduction
    #pragma unroll
    for (int o = 16; o; o >>= 1) {
        num += __shfl_down_sync(0xffffffffu, num, o);
        den += __shfl_down_sync(0xffffffffu, den, o);
    }
    if (lane == 0) { rn[w] = num; rd[w] = den; }
    __syncthreads();
    if (tid == 0) {
        float sn = 0.f, sd = 0.f;
        #pragma unroll
        for (int q = 0; q < 8; q++) { sn += rn[q]; sd += rd[q]; }
        g_num[side][b][k] = sn;
        g_den[side][b][k] = sd;
    }
}

// ---------------------------------------------------------------------------
// Finalize: loss = mean_b relu(score_n - score_p + margin).
// ---------------------------------------------------------------------------
__global__ void finalize_kernel(float* __restrict__ out) {
    const int b = threadIdx.x;  // 32 threads
    float sp = 0.f, sn = 0.f;
    #pragma unroll
    for (int k = 0; k < K_; k++) {
        sp += g_num[0][b][k] / g_den[0][b][k];
        sn += g_num[1][b][k] / g_den[1][b][k];
    }
    float v = fmaxf(sn - sp + 0.2f, 0.f);
    #pragma unroll
    for (int o = 16; o; o >>= 1) v += __shfl_down_sync(0xffffffffu, v, o);
    if (b == 0) out[0] = v * (1.0f / B_);
}

// ---------------------------------------------------------------------------
extern "C" void kernel_launch(void* const* d_in, const int* in_sizes, int n_in,
                              void* d_out, int out_size) {
    const float* he_anchor = (const float*)d_in[0];
    const float* he_pos    = (const float*)d_in[1];
    const float* he_neg    = (const float*)d_in[2];
    const float* W_a2h     = (const float*)d_in[3];
    const float* b_a2h     = (const float*)d_in[4];
    const float* W_c2h     = (const float*)d_in[5];
    const float* b_c2h     = (const float*)d_in[6];
    const float* W_att     = (const float*)d_in[7];
    // d_in[8] = b_att : cancels in softmax
    const float* W_fc      = (const float*)d_in[9];
    // d_in[10] = b_fc : cancels in score difference

    dim3 pgrid(4, 4, B_);
    proj_kernel<<<pgrid, 256>>>(he_anchor, W_a2h, b_a2h, 0);
    proj_kernel<<<pgrid, 256>>>(he_pos,    W_c2h, b_c2h, 1);
    proj_kernel<<<pgrid, 256>>>(he_neg,    W_c2h, b_c2h, 2);

    cpack_kernel<<<dim3(B_, 2), 256>>>();

    score_kernel<<<dim3(K_, B_, 2), 256>>>(W_att, W_fc);

    finalize_kernel<<<1, 32>>>((float*)d_out);
}

// round 6
// speedup vs baseline: 1.1307x; 1.1307x over previous
#include <cuda_runtime.h>
#include <cuda_bf16.h>
#include <cstdint>

// HGAN triplet loss:
//   score[b] = b_fc + sum_k num_k/den_k       (b_att cancels in softmax,
//   num_k = sum_{n,m} exp(S_k[n,m])*F_k[n,m],  b_fc cancels in score diff)
//   S_k[n,m] = sum_h W_att[k,h]*Aa[h,n]*Ac[h,m]
//   F_k[n,m] = sum_h W_fc [k,h]*Aa[h,n]*Ac[h,m]
// Score GEMMs on HMMA (mma.sync m16n8k16 bf16, fp32 acc) with 3-pass hi/lo
// bf16 splitting. Softmax epilogue uses hybrid MUFU(EX2) + FMA-pipe 2^f
// polynomial so both pipes saturate. C-pack fused into projection kernel.

#define B_ 32
#define N_ 256
#define E_ 300
#define H_ 256
#define K_ 8

// ---------------------------------------------------------------------------
// Device scratch (allocation-free per harness rules)
// ---------------------------------------------------------------------------
__device__ float    g_projT[B_][N_][H_];             // anchor proj, [n][h]
__device__ uint32_t g_Cpk[B_][2][2][256][128];       // [b][side][hi/lo][m][h/2]
__device__ float    g_pnum[2][B_][K_][2];
__device__ float    g_pden[2][B_][K_][2];

// ---------------------------------------------------------------------------
// Helpers
// ---------------------------------------------------------------------------
__device__ __forceinline__ uint32_t smem_u32(const void* p) {
    uint32_t a;
    asm("{ .reg .u64 t; cvta.to.shared.u64 t, %1; cvt.u32.u64 %0, t; }" : "=r"(a) : "l"(p));
    return a;
}
// pack (v0 -> low half, v1 -> high half) as bf16x2
__device__ __forceinline__ uint32_t cvt2(float v0, float v1) {
    uint32_t r;
    asm("cvt.rn.bf16x2.f32 %0, %1, %2;" : "=r"(r) : "f"(v1), "f"(v0));
    return r;
}
// hi/lo bf16 split of a pair of fp32 values
__device__ __forceinline__ void split2(float v0, float v1, uint32_t& uhi, uint32_t& ulo) {
    uhi = cvt2(v0, v1);
    float f0 = __uint_as_float(uhi << 16);
    float f1 = __uint_as_float(uhi & 0xffff0000u);
    ulo = cvt2(v0 - f0, v1 - f1);
}
__device__ __forceinline__ void ldsm4(uint32_t* r, uint32_t addr) {
    asm volatile("ldmatrix.sync.aligned.m8n8.x4.shared.b16 {%0,%1,%2,%3}, [%4];"
        : "=r"(r[0]), "=r"(r[1]), "=r"(r[2]), "=r"(r[3]) : "r"(addr));
}
__device__ __forceinline__ void mma_bf16(float* d, const uint32_t* a,
                                         uint32_t b0, uint32_t b1) {
    asm volatile("mma.sync.aligned.m16n8k16.row.col.f32.bf16.bf16.f32 "
        "{%0,%1,%2,%3}, {%4,%5,%6,%7}, {%8,%9}, {%0,%1,%2,%3};"
        : "+f"(d[0]), "+f"(d[1]), "+f"(d[2]), "+f"(d[3])
        : "r"(a[0]), "r"(a[1]), "r"(a[2]), "r"(a[3]), "r"(b0), "r"(b1));
}
// exp via 2^(x*log2e) with deg-5 minimax poly on [-0.5,0.5] (rel err ~3e-8).
// Runs on FMA/ALU pipes, freeing MUFU — used for half the values (hybrid).
__device__ __forceinline__ float exp_poly(float x) {
    float t = x * 1.4426950408889634f;
    float fi = rintf(t);
    float f = t - fi;
    float p = 0.00133335581f;
    p = fmaf(p, f, 0.00961804886f);
    p = fmaf(p, f, 0.0555041087f);
    p = fmaf(p, f, 0.240226507f);
    p = fmaf(p, f, 0.69314718056f);
    p = fmaf(p, f, 1.0f);
    float s = __int_as_float(((int)fi + 127) << 23);
    return p * s;
}

// ---------------------------------------------------------------------------
// Projection. mode 0 (anchor): writes g_projT[b][n][h].
// mode 1/2 (pos/neg): writes the hi/lo bf16 C-pack directly (cpack fused).
// ---------------------------------------------------------------------------
__global__ __launch_bounds__(256)
void proj_kernel(const float* __restrict__ X, const float* __restrict__ W,
                 const float* __restrict__ bias, int mode) {
    const int b  = blockIdx.z;
    const int h0 = blockIdx.y * 64;
    const int n0 = blockIdx.x * 64;
    const int tid = threadIdx.x;
    const int tx = tid & 15, ty = tid >> 4;

    __shared__ float Ws[20][68];
    __shared__ float Xs[20][68];

    float acc[4][4] = {};
    const float* Xb = X + (size_t)b * N_ * E_;

    for (int e0 = 0; e0 < E_; e0 += 20) {
        #pragma unroll
        for (int l = 0; l < 5; l++) {
            int idx = tid + l * 256;
            int rl = idx / 20;
            int el = idx - rl * 20;
            Ws[el][rl] = W [(h0 + rl) * E_ + e0 + el];
            Xs[el][rl] = Xb[(n0 + rl) * E_ + e0 + el];
        }
        __syncthreads();
        #pragma unroll
        for (int e = 0; e < 20; e++) {
            float4 wv4 = *(const float4*)&Ws[e][ty * 4];
            float4 xv4 = *(const float4*)&Xs[e][tx * 4];
            float wv[4] = {wv4.x, wv4.y, wv4.z, wv4.w};
            float xv[4] = {xv4.x, xv4.y, xv4.z, xv4.w};
            #pragma unroll
            for (int i = 0; i < 4; i++)
                #pragma unroll
                for (int j = 0; j < 4; j++)
                    acc[i][j] = fmaf(wv[i], xv[j], acc[i][j]);
        }
        __syncthreads();
    }

    float bb0 = bias[h0 + ty * 4 + 0];
    float bb1 = bias[h0 + ty * 4 + 1];
    float bb2 = bias[h0 + ty * 4 + 2];
    float bb3 = bias[h0 + ty * 4 + 3];

    if (mode == 0) {
        #pragma unroll
        for (int j = 0; j < 4; j++) {
            int n = n0 + tx * 4 + j;
            float4 o = make_float4(acc[0][j] + bb0, acc[1][j] + bb1,
                                   acc[2][j] + bb2, acc[3][j] + bb3);
            *(float4*)&g_projT[b][n][h0 + ty * 4] = o;
        }
    } else {
        const int side = mode - 1;
        const int hp = (h0 + ty * 4) >> 1;
        #pragma unroll
        for (int j = 0; j < 4; j++) {
            int n = n0 + tx * 4 + j;
            uint32_t hi, lo;
            split2(acc[0][j] + bb0, acc[1][j] + bb1, hi, lo);
            g_Cpk[b][side][0][n][hp + 0] = hi;
            g_Cpk[b][side][1][n][hp + 0] = lo;
            split2(acc[2][j] + bb2, acc[3][j] + bb3, hi, lo);
            g_Cpk[b][side][0][n][hp + 1] = hi;
            g_Cpk[b][side][1][n][hp + 1] = lo;
        }
    }
}

// ---------------------------------------------------------------------------
// Score: CTA per (k, nth, b, side); CTA covers n-rows [nth*128, +128) as two
// 64-row tiles, m in 2 tiles of 128. h streamed in chunks of 32.
// Warp w: n-rows 16*(w&3), m-cols 64*(w>>2) within a tile.
// ---------------------------------------------------------------------------
#define ASTR 20   // u32 stride per smem row (40 bf16 = 80 B, conflict-free)

__global__ __launch_bounds__(256, 2)
void score_kernel(const float* __restrict__ W_att, const float* __restrict__ W_fc) {
    __shared__ float watt_s[H_], wfc_s[H_];
    __shared__ uint32_t AShi[64 * ASTR], ASlo[64 * ASTR];
    __shared__ uint32_t AFhi[64 * ASTR], AFlo[64 * ASTR];
    __shared__ uint32_t Chi [128 * ASTR], Clo[128 * ASTR];
    __shared__ float rn[8], rd[8];

    const int tid  = threadIdx.x;
    const int lane = tid & 31, w = tid >> 5;
    const int k = blockIdx.x & 7, nth = blockIdx.x >> 3;
    const int b = blockIdx.y, side = blockIdx.z;

    for (int h = tid; h < H_; h += 256) {
        watt_s[h] = W_att[k * H_ + h];
        wfc_s[h]  = W_fc [k * H_ + h];
    }

    const float*    At = &g_projT[b][0][0];
    const uint32_t* Cp = &g_Cpk[b][side][0][0][0];

    const uint32_t aShb = smem_u32(AShi), aSlb = smem_u32(ASlo);
    const uint32_t aFhb = smem_u32(AFhi), aFlb = smem_u32(AFlo);
    const uint32_t cHb  = smem_u32(Chi),  cLb  = smem_u32(Clo);

    // fill-index precompute
    const int fa_n = tid >> 2, fa_i4 = (tid & 3) * 8;
    const int fc_var = tid >> 7, fc_m = tid & 127;
    uint32_t* fc_dst = (fc_var ? Clo : Chi) + fc_m * ASTR;

    // compute-index precompute
    const int wn0 = 16 * (w & 3), wm0 = 64 * (w >> 2);
    const uint32_t a_off = ((uint32_t)(wn0 + (lane & 15)) * ASTR * 4) + ((lane >> 4) << 4);
    const uint32_t c_row = (lane & 7) + ((lane >> 4) << 3);
    const uint32_t c_off = c_row * ASTR * 4 + (((lane >> 3) & 1) << 4);

    float num = 0.f, den = 0.f;

    for (int nt2 = 0; nt2 < 2; nt2++) {
      const int nt = nth * 2 + nt2;
      for (int mt = 0; mt < 2; mt++) {
        float accS[2][4][4], accF[2][4][4];
        #pragma unroll
        for (int mh = 0; mh < 2; mh++)
            #pragma unroll
            for (int g = 0; g < 4; g++)
                #pragma unroll
                for (int r = 0; r < 4; r++) { accS[mh][g][r] = 0.f; accF[mh][g][r] = 0.f; }

        for (int hc = 0; hc < 8; hc++) {
            const int h0 = hc * 32;
            __syncthreads();   // previous chunk's compute done

            // ---- A fill: 64n x 32h, scaled + split (8 h-values per thread)
            {
                const float* src = At + (nt * 64 + fa_n) * H_ + h0 + fa_i4;
                float4 v0 = *(const float4*)src;
                float4 v1 = *(const float4*)(src + 4);
                float4 a0 = *(const float4*)(watt_s + h0 + fa_i4);
                float4 a1 = *(const float4*)(watt_s + h0 + fa_i4 + 4);
                float4 f0 = *(const float4*)(wfc_s  + h0 + fa_i4);
                float4 f1 = *(const float4*)(wfc_s  + h0 + fa_i4 + 4);
                const int bi = fa_n * ASTR + (fa_i4 >> 1);
                uint32_t hi, lo;
                split2(a0.x * v0.x, a0.y * v0.y, hi, lo); AShi[bi + 0] = hi; ASlo[bi + 0] = lo;
                split2(a0.z * v0.z, a0.w * v0.w, hi, lo); AShi[bi + 1] = hi; ASlo[bi + 1] = lo;
                split2(a1.x * v1.x, a1.y * v1.y, hi, lo); AShi[bi + 2] = hi; ASlo[bi + 2] = lo;
                split2(a1.z * v1.z, a1.w * v1.w, hi, lo); AShi[bi + 3] = hi; ASlo[bi + 3] = lo;
                split2(f0.x * v0.x, f0.y * v0.y, hi, lo); AFhi[bi + 0] = hi; AFlo[bi + 0] = lo;
                split2(f0.z * v0.z, f0.w * v0.w, hi, lo); AFhi[bi + 1] = hi; AFlo[bi + 1] = lo;
                split2(f1.x * v1.x, f1.y * v1.y, hi, lo); AFhi[bi + 2] = hi; AFlo[bi + 2] = lo;
                split2(f1.z * v1.z, f1.w * v1.w, hi, lo); AFhi[bi + 3] = hi; AFlo[bi + 3] = lo;
            }
            // ---- C fill: copy packed hi/lo rows (16 u32 per thread)
            {
                const uint32_t* s = Cp + (fc_var * 256 + mt * 128 + fc_m) * 128 + (h0 >> 1);
                uint4 q0 = *(const uint4*)(s + 0);
                uint4 q1 = *(const uint4*)(s + 4);
                uint4 q2 = *(const uint4*)(s + 8);
                uint4 q3 = *(const uint4*)(s + 12);
                *(uint4*)(fc_dst + 0)  = q0;
                *(uint4*)(fc_dst + 4)  = q1;
                *(uint4*)(fc_dst + 8)  = q2;
                *(uint4*)(fc_dst + 12) = q3;
            }
            __syncthreads();   // fill visible

            // ---- HMMA compute
            #pragma unroll
            for (int ks = 0; ks < 2; ks++) {
                const uint32_t hkb = (uint32_t)(ks * 32);   // 16 bf16 = 32 bytes
                uint32_t aSh[4], aSl[4], aFh[4], aFl[4];
                ldsm4(aSh, aShb + a_off + hkb);
                ldsm4(aSl, aSlb + a_off + hkb);
                ldsm4(aFh, aFhb + a_off + hkb);
                ldsm4(aFl, aFlb + a_off + hkb);
                #pragma unroll
                for (int mh = 0; mh < 2; mh++) {
                    const uint32_t mrow = (uint32_t)(wm0 + mh * 32) * ASTR * 4;
                    uint32_t c[8];
                    ldsm4(c + 0, cHb + mrow + c_off + hkb);
                    ldsm4(c + 4, cHb + mrow + 16 * ASTR * 4 + c_off + hkb);
                    #pragma unroll
                    for (int g = 0; g < 4; g++) {
                        mma_bf16(accS[mh][g], aSh, c[2*g], c[2*g+1]);
                        mma_bf16(accS[mh][g], aSl, c[2*g], c[2*g+1]);
                        mma_bf16(accF[mh][g], aFh, c[2*g], c[2*g+1]);
                        mma_bf16(accF[mh][g], aFl, c[2*g], c[2*g+1]);
                    }
                    ldsm4(c + 0, cLb + mrow + c_off + hkb);
                    ldsm4(c + 4, cLb + mrow + 16 * ASTR * 4 + c_off + hkb);
                    #pragma unroll
                    for (int g = 0; g < 4; g++) {
                        mma_bf16(accS[mh][g], aSh, c[2*g], c[2*g+1]);
                        mma_bf16(accF[mh][g], aFh, c[2*g], c[2*g+1]);
                    }
                }
            }
        }

        // ---- epilogue: hybrid exp (even -> MUFU EX2, odd -> FMA-pipe poly)
        #pragma unroll
        for (int mh = 0; mh < 2; mh++)
            #pragma unroll
            for (int g = 0; g < 4; g++)
                #pragma unroll
                for (int r = 0; r < 4; r++) {
                    float S = accS[mh][g][r];
                    float e = (r & 1) ? exp_poly(S) : __expf(S);
                    den += e;
                    num = fmaf(e, accF[mh][g][r], num);
                }
      }
    }

    // block reduction
    #pragma unroll
    for (int o = 16; o; o >>= 1) {
        num += __shfl_down_sync(0xffffffffu, num, o);
        den += __shfl_down_sync(0xffffffffu, den, o);
    }
    if (lane == 0) { rn[w] = num; rd[w] = den; }
    __syncthreads();
    if (tid == 0) {
        float sn = 0.f, sd = 0.f;
        #pragma unroll
        for (int q = 0; q < 8; q++) { sn += rn[q]; sd += rd[q]; }
        g_pnum[side][b][k][nth] = sn;
        g_pden[side][b][k][nth] = sd;
    }
}

// ---------------------------------------------------------------------------
// Finalize: loss = mean_b relu(score_n - score_p + margin).
// ---------------------------------------------------------------------------
__global__ void finalize_kernel(float* __restrict__ out) {
    const int b = threadIdx.x;  // 32 threads
    float sp = 0.f, sn = 0.f;
    #pragma unroll
    for (int k = 0; k < K_; k++) {
        float n0 = g_pnum[0][b][k][0] + g_pnum[0][b][k][1];
        float d0 = g_pden[0][b][k][0] + g_pden[0][b][k][1];
        float n1 = g_pnum[1][b][k][0] + g_pnum[1][b][k][1];
        float d1 = g_pden[1][b][k][0] + g_pden[1][b][k][1];
        sp += n0 / d0;
        sn += n1 / d1;
    }
    float v = fmaxf(sn - sp + 0.2f, 0.f);
    #pragma unroll
    for (int o = 16; o; o >>= 1) v += __shfl_down_sync(0xffffffffu, v, o);
    if (b == 0) out[0] = v * (1.0f / B_);
}

// ---------------------------------------------------------------------------
extern "C" void kernel_launch(void* const* d_in, const int* in_sizes, int n_in,
                              void* d_out, int out_size) {
    const float* he_anchor = (const float*)d_in[0];
    const float* he_pos    = (const float*)d_in[1];
    const float* he_neg    = (const float*)d_in[2];
    const float* W_a2h     = (const float*)d_in[3];
    const float* b_a2h     = (const float*)d_in[4];
    const float* W_c2h     = (const float*)d_in[5];
    const float* b_c2h     = (const float*)d_in[6];
    const float* W_att     = (const float*)d_in[7];
    // d_in[8] = b_att : cancels in softmax
    const float* W_fc      = (const float*)d_in[9];
    // d_in[10] = b_fc : cancels in score difference

    dim3 pgrid(4, 4, B_);
    proj_kernel<<<pgrid, 256>>>(he_anchor, W_a2h, b_a2h, 0);
    proj_kernel<<<pgrid, 256>>>(he_pos,    W_c2h, b_c2h, 1);
    proj_kernel<<<pgrid, 256>>>(he_neg,    W_c2h, b_c2h, 2);

    score_kernel<<<dim3(16, B_, 2), 256>>>(W_att, W_fc);

    finalize_kernel<<<1, 32>>>((float*)d_out);
}

// round 7
// speedup vs baseline: 1.1327x; 1.0018x over previous
#include <cuda_runtime.h>
#include <cuda_bf16.h>
#include <cstdint>

// HGAN triplet loss:
//   score[b] = b_fc + sum_k num_k/den_k       (b_att cancels in softmax,
//   num_k = sum_{n,m} exp(S_k[n,m])*F_k[n,m],  b_fc cancels in score diff)
//   S_k[n,m] = sum_h W_att[k,h]*Aa[h,n]*Ac[h,m]
//   F_k[n,m] = sum_h W_fc [k,h]*Aa[h,n]*Ac[h,m]
// Score GEMMs on HMMA (mma.sync m16n8k16 bf16, fp32 acc) with 3-pass hi/lo
// bf16 splitting. Softmax epilogue uses hybrid MUFU(EX2) + FMA-pipe 2^f
// polynomial so both pipes saturate. C-pack fused into projection kernel.

#define B_ 32
#define N_ 256
#define E_ 300
#define H_ 256
#define K_ 8

// ---------------------------------------------------------------------------
// Device scratch (allocation-free per harness rules)
// ---------------------------------------------------------------------------
__device__ float    g_projT[B_][N_][H_];             // anchor proj, [n][h]
__device__ uint32_t g_Cpk[B_][2][2][256][128];       // [b][side][hi/lo][m][h/2]
__device__ float    g_pnum[2][B_][K_][2];
__device__ float    g_pden[2][B_][K_][2];

// ---------------------------------------------------------------------------
// Helpers
// ---------------------------------------------------------------------------
__device__ __forceinline__ uint32_t smem_u32(const void* p) {
    uint32_t a;
    asm("{ .reg .u64 t; cvta.to.shared.u64 t, %1; cvt.u32.u64 %0, t; }" : "=r"(a) : "l"(p));
    return a;
}
// pack (v0 -> low half, v1 -> high half) as bf16x2
__device__ __forceinline__ uint32_t cvt2(float v0, float v1) {
    uint32_t r;
    asm("cvt.rn.bf16x2.f32 %0, %1, %2;" : "=r"(r) : "f"(v1), "f"(v0));
    return r;
}
// hi/lo bf16 split of a pair of fp32 values
__device__ __forceinline__ void split2(float v0, float v1, uint32_t& uhi, uint32_t& ulo) {
    uhi = cvt2(v0, v1);
    float f0 = __uint_as_float(uhi << 16);
    float f1 = __uint_as_float(uhi & 0xffff0000u);
    ulo = cvt2(v0 - f0, v1 - f1);
}
__device__ __forceinline__ void ldsm4(uint32_t* r, uint32_t addr) {
    asm volatile("ldmatrix.sync.aligned.m8n8.x4.shared.b16 {%0,%1,%2,%3}, [%4];"
        : "=r"(r[0]), "=r"(r[1]), "=r"(r[2]), "=r"(r[3]) : "r"(addr));
}
__device__ __forceinline__ void mma_bf16(float* d, const uint32_t* a,
                                         uint32_t b0, uint32_t b1) {
    asm volatile("mma.sync.aligned.m16n8k16.row.col.f32.bf16.bf16.f32 "
        "{%0,%1,%2,%3}, {%4,%5,%6,%7}, {%8,%9}, {%0,%1,%2,%3};"
        : "+f"(d[0]), "+f"(d[1]), "+f"(d[2]), "+f"(d[3])
        : "r"(a[0]), "r"(a[1]), "r"(a[2]), "r"(a[3]), "r"(b0), "r"(b1));
}
// exp via 2^(x*log2e) with deg-5 minimax poly on [-0.5,0.5] (rel err ~3e-8).
// Runs on FMA/ALU pipes, freeing MUFU — used for half the values (hybrid).
__device__ __forceinline__ float exp_poly(float x) {
    float t = x * 1.4426950408889634f;
    float fi = rintf(t);
    float f = t - fi;
    float p = 0.00133335581f;
    p = fmaf(p, f, 0.00961804886f);
    p = fmaf(p, f, 0.0555041087f);
    p = fmaf(p, f, 0.240226507f);
    p = fmaf(p, f, 0.69314718056f);
    p = fmaf(p, f, 1.0f);
    float s = __int_as_float(((int)fi + 127) << 23);
    return p * s;
}

// ---------------------------------------------------------------------------
// Projection. mode 0 (anchor): writes g_projT[b][n][h].
// mode 1/2 (pos/neg): writes the hi/lo bf16 C-pack directly (cpack fused).
// ---------------------------------------------------------------------------
__global__ __launch_bounds__(256)
void proj_kernel(const float* __restrict__ X, const float* __restrict__ W,
                 const float* __restrict__ bias, int mode) {
    const int b  = blockIdx.z;
    const int h0 = blockIdx.y * 64;
    const int n0 = blockIdx.x * 64;
    const int tid = threadIdx.x;
    const int tx = tid & 15, ty = tid >> 4;

    __shared__ float Ws[20][68];
    __shared__ float Xs[20][68];

    float acc[4][4] = {};
    const float* Xb = X + (size_t)b * N_ * E_;

    for (int e0 = 0; e0 < E_; e0 += 20) {
        #pragma unroll
        for (int l = 0; l < 5; l++) {
            int idx = tid + l * 256;
            int rl = idx / 20;
            int el = idx - rl * 20;
            Ws[el][rl] = W [(h0 + rl) * E_ + e0 + el];
            Xs[el][rl] = Xb[(n0 + rl) * E_ + e0 + el];
        }
        __syncthreads();
        #pragma unroll
        for (int e = 0; e < 20; e++) {
            float4 wv4 = *(const float4*)&Ws[e][ty * 4];
            float4 xv4 = *(const float4*)&Xs[e][tx * 4];
            float wv[4] = {wv4.x, wv4.y, wv4.z, wv4.w};
            float xv[4] = {xv4.x, xv4.y, xv4.z, xv4.w};
            #pragma unroll
            for (int i = 0; i < 4; i++)
                #pragma unroll
                for (int j = 0; j < 4; j++)
                    acc[i][j] = fmaf(wv[i], xv[j], acc[i][j]);
        }
        __syncthreads();
    }

    float bb0 = bias[h0 + ty * 4 + 0];
    float bb1 = bias[h0 + ty * 4 + 1];
    float bb2 = bias[h0 + ty * 4 + 2];
    float bb3 = bias[h0 + ty * 4 + 3];

    if (mode == 0) {
        #pragma unroll
        for (int j = 0; j < 4; j++) {
            int n = n0 + tx * 4 + j;
            float4 o = make_float4(acc[0][j] + bb0, acc[1][j] + bb1,
                                   acc[2][j] + bb2, acc[3][j] + bb3);
            *(float4*)&g_projT[b][n][h0 + ty * 4] = o;
        }
    } else {
        const int side = mode - 1;
        const int hp = (h0 + ty * 4) >> 1;
        #pragma unroll
        for (int j = 0; j < 4; j++) {
            int n = n0 + tx * 4 + j;
            uint32_t hi, lo;
            split2(acc[0][j] + bb0, acc[1][j] + bb1, hi, lo);
            g_Cpk[b][side][0][n][hp + 0] = hi;
            g_Cpk[b][side][1][n][hp + 0] = lo;
            split2(acc[2][j] + bb2, acc[3][j] + bb3, hi, lo);
            g_Cpk[b][side][0][n][hp + 1] = hi;
            g_Cpk[b][side][1][n][hp + 1] = lo;
        }
    }
}

// ---------------------------------------------------------------------------
// Score: CTA per (k, nth, b, side); CTA covers n-rows [nth*128, +128) as two
// 64-row tiles, m in 2 tiles of 128. h streamed in chunks of 32.
// Warp w: n-rows 16*(w&3), m-cols 64*(w>>2) within a tile.
// ---------------------------------------------------------------------------
#define ASTR 20   // u32 stride per smem row (40 bf16 = 80 B, conflict-free)

__global__ __launch_bounds__(256, 2)
void score_kernel(const float* __restrict__ W_att, const float* __restrict__ W_fc) {
    __shared__ float watt_s[H_], wfc_s[H_];
    __shared__ uint32_t AShi[64 * ASTR], ASlo[64 * ASTR];
    __shared__ uint32_t AFhi[64 * ASTR], AFlo[64 * ASTR];
    __shared__ uint32_t Chi [128 * ASTR], Clo[128 * ASTR];
    __shared__ float rn[8], rd[8];

    const int tid  = threadIdx.x;
    const int lane = tid & 31, w = tid >> 5;
    const int k = blockIdx.x & 7, nth = blockIdx.x >> 3;
    const int b = blockIdx.y, side = blockIdx.z;

    for (int h = tid; h < H_; h += 256) {
        watt_s[h] = W_att[k * H_ + h];
        wfc_s[h]  = W_fc [k * H_ + h];
    }

    const float*    At = &g_projT[b][0][0];
    const uint32_t* Cp = &g_Cpk[b][side][0][0][0];

    const uint32_t aShb = smem_u32(AShi), aSlb = smem_u32(ASlo);
    const uint32_t aFhb = smem_u32(AFhi), aFlb = smem_u32(AFlo);
    const uint32_t cHb  = smem_u32(Chi),  cLb  = smem_u32(Clo);

    // fill-index precompute
    const int fa_n = tid >> 2, fa_i4 = (tid & 3) * 8;
    const int fc_var = tid >> 7, fc_m = tid & 127;
    uint32_t* fc_dst = (fc_var ? Clo : Chi) + fc_m * ASTR;

    // compute-index precompute
    const int wn0 = 16 * (w & 3), wm0 = 64 * (w >> 2);
    const uint32_t a_off = ((uint32_t)(wn0 + (lane & 15)) * ASTR * 4) + ((lane >> 4) << 4);
    const uint32_t c_row = (lane & 7) + ((lane >> 4) << 3);
    const uint32_t c_off = c_row * ASTR * 4 + (((lane >> 3) & 1) << 4);

    float num = 0.f, den = 0.f;

    for (int nt2 = 0; nt2 < 2; nt2++) {
      const int nt = nth * 2 + nt2;
      for (int mt = 0; mt < 2; mt++) {
        float accS[2][4][4], accF[2][4][4];
        #pragma unroll
        for (int mh = 0; mh < 2; mh++)
            #pragma unroll
            for (int g = 0; g < 4; g++)
                #pragma unroll
                for (int r = 0; r < 4; r++) { accS[mh][g][r] = 0.f; accF[mh][g][r] = 0.f; }

        for (int hc = 0; hc < 8; hc++) {
            const int h0 = hc * 32;
            __syncthreads();   // previous chunk's compute done

            // ---- A fill: 64n x 32h, scaled + split (8 h-values per thread)
            {
                const float* src = At + (nt * 64 + fa_n) * H_ + h0 + fa_i4;
                float4 v0 = *(const float4*)src;
                float4 v1 = *(const float4*)(src + 4);
                float4 a0 = *(const float4*)(watt_s + h0 + fa_i4);
                float4 a1 = *(const float4*)(watt_s + h0 + fa_i4 + 4);
                float4 f0 = *(const float4*)(wfc_s  + h0 + fa_i4);
                float4 f1 = *(const float4*)(wfc_s  + h0 + fa_i4 + 4);
                const int bi = fa_n * ASTR + (fa_i4 >> 1);
                uint32_t hi, lo;
                split2(a0.x * v0.x, a0.y * v0.y, hi, lo); AShi[bi + 0] = hi; ASlo[bi + 0] = lo;
                split2(a0.z * v0.z, a0.w * v0.w, hi, lo); AShi[bi + 1] = hi; ASlo[bi + 1] = lo;
                split2(a1.x * v1.x, a1.y * v1.y, hi, lo); AShi[bi + 2] = hi; ASlo[bi + 2] = lo;
                split2(a1.z * v1.z, a1.w * v1.w, hi, lo); AShi[bi + 3] = hi; ASlo[bi + 3] = lo;
                split2(f0.x * v0.x, f0.y * v0.y, hi, lo); AFhi[bi + 0] = hi; AFlo[bi + 0] = lo;
                split2(f0.z * v0.z, f0.w * v0.w, hi, lo); AFhi[bi + 1] = hi; AFlo[bi + 1] = lo;
                split2(f1.x * v1.x, f1.y * v1.y, hi, lo); AFhi[bi + 2] = hi; AFlo[bi + 2] = lo;
                split2(f1.z * v1.z, f1.w * v1.w, hi, lo); AFhi[bi + 3] = hi; AFlo[bi + 3] = lo;
            }
            // ---- C fill: copy packed hi/lo rows (16 u32 per thread)
            {
                const uint32_t* s = Cp + (fc_var * 256 + mt * 128 + fc_m) * 128 + (h0 >> 1);
                uint4 q0 = *(const uint4*)(s + 0);
                uint4 q1 = *(const uint4*)(s + 4);
                uint4 q2 = *(const uint4*)(s + 8);
                uint4 q3 = *(const uint4*)(s + 12);
                *(uint4*)(fc_dst + 0)  = q0;
                *(uint4*)(fc_dst + 4)  = q1;
                *(uint4*)(fc_dst + 8)  = q2;
                *(uint4*)(fc_dst + 12) = q3;
            }
            __syncthreads();   // fill visible

            // ---- HMMA compute
            #pragma unroll
            for (int ks = 0; ks < 2; ks++) {
                const uint32_t hkb = (uint32_t)(ks * 32);   // 16 bf16 = 32 bytes
                uint32_t aSh[4], aSl[4], aFh[4], aFl[4];
                ldsm4(aSh, aShb + a_off + hkb);
                ldsm4(aSl, aSlb + a_off + hkb);
                ldsm4(aFh, aFhb + a_off + hkb);
                ldsm4(aFl, aFlb + a_off + hkb);
                #pragma unroll
                for (int mh = 0; mh < 2; mh++) {
                    const uint32_t mrow = (uint32_t)(wm0 + mh * 32) * ASTR * 4;
                    uint32_t c[8];
                    ldsm4(c + 0, cHb + mrow + c_off + hkb);
                    ldsm4(c + 4, cHb + mrow + 16 * ASTR * 4 + c_off + hkb);
                    #pragma unroll
                    for (int g = 0; g < 4; g++) {
                        mma_bf16(accS[mh][g], aSh, c[2*g], c[2*g+1]);
                        mma_bf16(accS[mh][g], aSl, c[2*g], c[2*g+1]);
                        mma_bf16(accF[mh][g], aFh, c[2*g], c[2*g+1]);
                        mma_bf16(accF[mh][g], aFl, c[2*g], c[2*g+1]);
                    }
                    ldsm4(c + 0, cLb + mrow + c_off + hkb);
                    ldsm4(c + 4, cLb + mrow + 16 * ASTR * 4 + c_off + hkb);
                    #pragma unroll
                    for (int g = 0; g < 4; g++) {
                        mma_bf16(accS[mh][g], aSh, c[2*g], c[2*g+1]);
                        mma_bf16(accF[mh][g], aFh, c[2*g], c[2*g+1]);
                    }
                }
            }
        }

        // ---- epilogue: hybrid exp (even -> MUFU EX2, odd -> FMA-pipe poly)
        #pragma unroll
        for (int mh = 0; mh < 2; mh++)
            #pragma unroll
            for (int g = 0; g < 4; g++)
                #pragma unroll
                for (int r = 0; r < 4; r++) {
                    float S = accS[mh][g][r];
                    float e = (r & 1) ? exp_poly(S) : __expf(S);
                    den += e;
                    num = fmaf(e, accF[mh][g][r], num);
                }
      }
    }

    // block reduction
    #pragma unroll
    for (int o = 16; o; o >>= 1) {
        num += __shfl_down_sync(0xffffffffu, num, o);
        den += __shfl_down_sync(0xffffffffu, den, o);
    }
    if (lane == 0) { rn[w] = num; rd[w] = den; }
    __syncthreads();
    if (tid == 0) {
        float sn = 0.f, sd = 0.f;
        #pragma unroll
        for (int q = 0; q < 8; q++) { sn += rn[q]; sd += rd[q]; }
        g_pnum[side][b][k][nth] = sn;
        g_pden[side][b][k][nth] = sd;
    }
}

// ---------------------------------------------------------------------------
// Finalize: loss = mean_b relu(score_n - score_p + margin).
// ---------------------------------------------------------------------------
__global__ void finalize_kernel(float* __restrict__ out) {
    const int b = threadIdx.x;  // 32 threads
    float sp = 0.f, sn = 0.f;
    #pragma unroll
    for (int k = 0; k < K_; k++) {
        float n0 = g_pnum[0][b][k][0] + g_pnum[0][b][k][1];
        float d0 = g_pden[0][b][k][0] + g_pden[0][b][k][1];
        float n1 = g_pnum[1][b][k][0] + g_pnum[1][b][k][1];
        float d1 = g_pden[1][b][k][0] + g_pden[1][b][k][1];
        sp += n0 / d0;
        sn += n1 / d1;
    }
    float v = fmaxf(sn - sp + 0.2f, 0.f);
    #pragma unroll
    for (int o = 16; o; o >>= 1) v += __shfl_down_sync(0xffffffffu, v, o);
    if (b == 0) out[0] = v * (1.0f / B_);
}

// ---------------------------------------------------------------------------
extern "C" void kernel_launch(void* const* d_in, const int* in_sizes, int n_in,
                              void* d_out, int out_size) {
    const float* he_anchor = (const float*)d_in[0];
    const float* he_pos    = (const float*)d_in[1];
    const float* he_neg    = (const float*)d_in[2];
    const float* W_a2h     = (const float*)d_in[3];
    const float* b_a2h     = (const float*)d_in[4];
    const float* W_c2h     = (const float*)d_in[5];
    const float* b_c2h     = (const float*)d_in[6];
    const float* W_att     = (const float*)d_in[7];
    // d_in[8] = b_att : cancels in softmax
    const float* W_fc      = (const float*)d_in[9];
    // d_in[10] = b_fc : cancels in score difference

    dim3 pgrid(4, 4, B_);
    proj_kernel<<<pgrid, 256>>>(he_anchor, W_a2h, b_a2h, 0);
    proj_kernel<<<pgrid, 256>>>(he_pos,    W_c2h, b_c2h, 1);
    proj_kernel<<<pgrid, 256>>>(he_neg,    W_c2h, b_c2h, 2);

    score_kernel<<<dim3(16, B_, 2), 256>>>(W_att, W_fc);

    finalize_kernel<<<1, 32>>>((float*)d_out);
}

// round 8
// speedup vs baseline: 1.5311x; 1.3517x over previous
#include <cuda_runtime.h>
#include <cuda_bf16.h>
#include <cstdint>

// HGAN triplet loss:
//   score[b] = b_fc + sum_k num_k/den_k       (b_att cancels in softmax,
//   num_k = sum_{n,m} exp(S_k[n,m])*F_k[n,m],  b_fc cancels in score diff)
//   S_k[n,m] = sum_h W_att[k,h]*Aa[h,n]*Ac[h,m]
//   F_k[n,m] = sum_h W_fc [k,h]*Aa[h,n]*Ac[h,m]
// HMMA (m16n8k16 bf16, fp32 acc), 3-pass hi/lo split. A-operand fragments are
// built directly in registers (scale+split from fp32 anchor proj) — no A smem,
// no A ldmatrix. C-operand comes pre-split from proj via smem+ldmatrix.

#define B_ 32
#define N_ 256
#define E_ 300
#define H_ 256
#define K_ 8

// ---------------------------------------------------------------------------
// Device scratch (allocation-free per harness rules)
// ---------------------------------------------------------------------------
__device__ float    g_projT[B_][N_][H_];             // anchor proj, [n][h]
__device__ uint32_t g_Cpk[B_][2][2][256][128];       // [b][side][hi/lo][m][h/2]
__device__ float    g_pnum[2][B_][K_][8];
__device__ float    g_pden[2][B_][K_][8];

// ---------------------------------------------------------------------------
// Helpers
// ---------------------------------------------------------------------------
__device__ __forceinline__ uint32_t smem_u32(const void* p) {
    uint32_t a;
    asm("{ .reg .u64 t; cvta.to.shared.u64 t, %1; cvt.u32.u64 %0, t; }" : "=r"(a) : "l"(p));
    return a;
}
// pack (v0 -> low half, v1 -> high half) as bf16x2
__device__ __forceinline__ uint32_t cvt2(float v0, float v1) {
    uint32_t r;
    asm("cvt.rn.bf16x2.f32 %0, %1, %2;" : "=r"(r) : "f"(v1), "f"(v0));
    return r;
}
// hi/lo bf16 split of a pair of fp32 values
__device__ __forceinline__ void split2(float v0, float v1, uint32_t& uhi, uint32_t& ulo) {
    uhi = cvt2(v0, v1);
    float f0 = __uint_as_float(uhi << 16);
    float f1 = __uint_as_float(uhi & 0xffff0000u);
    ulo = cvt2(v0 - f0, v1 - f1);
}
__device__ __forceinline__ void ldsm4(uint32_t* r, uint32_t addr) {
    asm volatile("ldmatrix.sync.aligned.m8n8.x4.shared.b16 {%0,%1,%2,%3}, [%4];"
        : "=r"(r[0]), "=r"(r[1]), "=r"(r[2]), "=r"(r[3]) : "r"(addr));
}
__device__ __forceinline__ void mma_bf16(float* d, const uint32_t* a,
                                         uint32_t b0, uint32_t b1) {
    asm volatile("mma.sync.aligned.m16n8k16.row.col.f32.bf16.bf16.f32 "
        "{%0,%1,%2,%3}, {%4,%5,%6,%7}, {%8,%9}, {%0,%1,%2,%3};"
        : "+f"(d[0]), "+f"(d[1]), "+f"(d[2]), "+f"(d[3])
        : "r"(a[0]), "r"(a[1]), "r"(a[2]), "r"(a[3]), "r"(b0), "r"(b1));
}
// exp via 2^(x*log2e), deg-5 minimax poly (rel err ~3e-8), FMA-pipe only.
__device__ __forceinline__ float exp_poly(float x) {
    float t = x * 1.4426950408889634f;
    float fi = rintf(t);
    float f = t - fi;
    float p = 0.00133335581f;
    p = fmaf(p, f, 0.00961804886f);
    p = fmaf(p, f, 0.0555041087f);
    p = fmaf(p, f, 0.240226507f);
    p = fmaf(p, f, 0.69314718056f);
    p = fmaf(p, f, 1.0f);
    float s = __int_as_float(((int)fi + 127) << 23);
    return p * s;
}

// ---------------------------------------------------------------------------
// Projection, all three inputs in ONE launch (grid z = 96; mode = z/32).
// mode 0 (anchor): writes g_projT[b][n][h] fp32.
// mode 1/2 (pos/neg): writes the hi/lo bf16 C-pack directly.
// ---------------------------------------------------------------------------
__global__ __launch_bounds__(256)
void proj_kernel(const float* __restrict__ Xa, const float* __restrict__ Xp,
                 const float* __restrict__ Xn,
                 const float* __restrict__ Wa, const float* __restrict__ ba,
                 const float* __restrict__ Wc, const float* __restrict__ bc) {
    const int mode = blockIdx.z >> 5;
    const int b    = blockIdx.z & 31;
    const int h0 = blockIdx.y * 64;
    const int n0 = blockIdx.x * 64;
    const int tid = threadIdx.x;
    const int tx = tid & 15, ty = tid >> 4;

    const float* X    = (mode == 0) ? Xa : (mode == 1 ? Xp : Xn);
    const float* W    = (mode == 0) ? Wa : Wc;
    const float* bias = (mode == 0) ? ba : bc;

    __shared__ float Ws[20][68];
    __shared__ float Xs[20][68];

    float acc[4][4] = {};
    const float* Xb = X + (size_t)b * N_ * E_;

    for (int e0 = 0; e0 < E_; e0 += 20) {
        #pragma unroll
        for (int l = 0; l < 5; l++) {
            int idx = tid + l * 256;
            int rl = idx / 20;
            int el = idx - rl * 20;
            Ws[el][rl] = W [(h0 + rl) * E_ + e0 + el];
            Xs[el][rl] = Xb[(n0 + rl) * E_ + e0 + el];
        }
        __syncthreads();
        #pragma unroll
        for (int e = 0; e < 20; e++) {
            float4 wv4 = *(const float4*)&Ws[e][ty * 4];
            float4 xv4 = *(const float4*)&Xs[e][tx * 4];
            float wv[4] = {wv4.x, wv4.y, wv4.z, wv4.w};
            float xv[4] = {xv4.x, xv4.y, xv4.z, xv4.w};
            #pragma unroll
            for (int i = 0; i < 4; i++)
                #pragma unroll
                for (int j = 0; j < 4; j++)
                    acc[i][j] = fmaf(wv[i], xv[j], acc[i][j]);
        }
        __syncthreads();
    }

    float bb0 = bias[h0 + ty * 4 + 0];
    float bb1 = bias[h0 + ty * 4 + 1];
    float bb2 = bias[h0 + ty * 4 + 2];
    float bb3 = bias[h0 + ty * 4 + 3];

    if (mode == 0) {
        #pragma unroll
        for (int j = 0; j < 4; j++) {
            int n = n0 + tx * 4 + j;
            float4 o = make_float4(acc[0][j] + bb0, acc[1][j] + bb1,
                                   acc[2][j] + bb2, acc[3][j] + bb3);
            *(float4*)&g_projT[b][n][h0 + ty * 4] = o;
        }
    } else {
        const int side = mode - 1;
        const int hp = (h0 + ty * 4) >> 1;
        #pragma unroll
        for (int j = 0; j < 4; j++) {
            int n = n0 + tx * 4 + j;
            uint32_t hi, lo;
            split2(acc[0][j] + bb0, acc[1][j] + bb1, hi, lo);
            g_Cpk[b][side][0][n][hp + 0] = hi;
            g_Cpk[b][side][1][n][hp + 0] = lo;
            split2(acc[2][j] + bb2, acc[3][j] + bb3, hi, lo);
            g_Cpk[b][side][0][n][hp + 1] = hi;
            g_Cpk[b][side][1][n][hp + 1] = lo;
        }
    }
}

// ---------------------------------------------------------------------------
// Score: CTA = 128n x 64m slice of one (k, b, side). bx = k + 8*mq + 32*nh.
// Warp w covers n rows [nh*128 + 16w, +16), all 64 m. h streamed in 8 chunks
// of 32. A fragments built in registers (LDG fp32 -> scale -> hi/lo split);
// C fragments from smem via ldmatrix (pre-split global pack).
// ---------------------------------------------------------------------------
#define ASTR 20   // u32 stride per smem row (40 bf16 = 80 B, conflict-free)

__global__ __launch_bounds__(256, 2)
void score_kernel(const float* __restrict__ W_att, const float* __restrict__ W_fc) {
    __shared__ float watt_s[H_], wfc_s[H_];
    __shared__ uint32_t Chi[64 * ASTR], Clo[64 * ASTR];
    __shared__ float rn[8], rd[8];

    const int tid  = threadIdx.x;
    const int lane = tid & 31, w = tid >> 5;
    const int k  = blockIdx.x & 7;
    const int mq = (blockIdx.x >> 3) & 3;
    const int nh = blockIdx.x >> 5;
    const int b = blockIdx.y, side = blockIdx.z;

    for (int h = tid; h < H_; h += 256) {
        watt_s[h] = W_att[k * H_ + h];
        wfc_s[h]  = W_fc [k * H_ + h];
    }

    const float*    At = &g_projT[b][0][0];
    const uint32_t* Cp = &g_Cpk[b][side][0][0][0];
    const uint32_t cHb = smem_u32(Chi), cLb = smem_u32(Clo);

    // C fill indices: 2 uint4 per thread per chunk
    const int f_var = tid >> 7;                 // 0: hi, 1: lo  (idx=tid covers var0+half var... see loop)
    // (computed per-iteration below)

    // compute-index precompute
    const int g = lane >> 2, t = lane & 3;
    const int n_r0 = nh * 128 + 16 * w + g;     // A frag rows
    const int n_r1 = n_r0 + 8;
    const uint32_t c_row = (lane & 7) + ((lane >> 4) << 3);
    const uint32_t c_off = c_row * ASTR * 4 + (((lane >> 3) & 1) << 4);

    float accS[2][4][4], accF[2][4][4];
    #pragma unroll
    for (int mh = 0; mh < 2; mh++)
        #pragma unroll
        for (int gg = 0; gg < 4; gg++)
            #pragma unroll
            for (int r = 0; r < 4; r++) { accS[mh][gg][r] = 0.f; accF[mh][gg][r] = 0.f; }

    for (int hc = 0; hc < 8; hc++) {
        const int h0 = hc * 32;
        __syncthreads();   // previous chunk's ldsm done (also covers watt_s first pass)

        // ---- C fill: 64m x 32h, hi+lo = 4096 u32 -> 2 uint4 per thread
        #pragma unroll
        for (int i = 0; i < 2; i++) {
            int idx = tid + i * 256;            // 0..511
            int var = idx >> 8;
            int rem = idx & 255;
            int m = rem >> 2, q = rem & 3;
            uint4 v = *(const uint4*)(Cp + ((var * 2 * 256) ? 0 : 0)
                                        + (size_t)var * 256 * 128
                                        + (size_t)(mq * 64 + m) * 128 + hc * 16 + q * 4);
            uint32_t* dst = (var ? Clo : Chi) + m * ASTR + q * 4;
            *(uint4*)dst = v;
        }
        __syncthreads();

        #pragma unroll
        for (int ks = 0; ks < 2; ks++) {
            const int h0k = h0 + ks * 16;
            // ---- A fragments in registers: load fp32 pairs, scale, split
            float2 v00 = *(const float2*)(At + n_r0 * H_ + h0k + 2 * t);
            float2 v10 = *(const float2*)(At + n_r1 * H_ + h0k + 2 * t);
            float2 v01 = *(const float2*)(At + n_r0 * H_ + h0k + 2 * t + 8);
            float2 v11 = *(const float2*)(At + n_r1 * H_ + h0k + 2 * t + 8);
            float2 wa0 = *(const float2*)(watt_s + h0k + 2 * t);
            float2 wa1 = *(const float2*)(watt_s + h0k + 2 * t + 8);
            float2 wf0 = *(const float2*)(wfc_s  + h0k + 2 * t);
            float2 wf1 = *(const float2*)(wfc_s  + h0k + 2 * t + 8);

            uint32_t aSh[4], aSl[4], aFh[4], aFl[4];
            split2(wa0.x * v00.x, wa0.y * v00.y, aSh[0], aSl[0]);
            split2(wa0.x * v10.x, wa0.y * v10.y, aSh[1], aSl[1]);
            split2(wa1.x * v01.x, wa1.y * v01.y, aSh[2], aSl[2]);
            split2(wa1.x * v11.x, wa1.y * v11.y, aSh[3], aSl[3]);
            split2(wf0.x * v00.x, wf0.y * v00.y, aFh[0], aFl[0]);
            split2(wf0.x * v10.x, wf0.y * v10.y, aFh[1], aFl[1]);
            split2(wf1.x * v01.x, wf1.y * v01.y, aFh[2], aFl[2]);
            split2(wf1.x * v11.x, wf1.y * v11.y, aFh[3], aFl[3]);

            const uint32_t hkb = (uint32_t)(ks * 32);
            #pragma unroll
            for (int mh = 0; mh < 2; mh++) {
                const uint32_t mrow = (uint32_t)(mh * 32) * ASTR * 4;
                uint32_t c[8];
                ldsm4(c + 0, cHb + mrow + c_off + hkb);
                ldsm4(c + 4, cHb + mrow + 16 * ASTR * 4 + c_off + hkb);
                #pragma unroll
                for (int gg = 0; gg < 4; gg++) {
                    mma_bf16(accS[mh][gg], aSh, c[2*gg], c[2*gg+1]);
                    mma_bf16(accS[mh][gg], aSl, c[2*gg], c[2*gg+1]);
                    mma_bf16(accF[mh][gg], aFh, c[2*gg], c[2*gg+1]);
                    mma_bf16(accF[mh][gg], aFl, c[2*gg], c[2*gg+1]);
                }
                ldsm4(c + 0, cLb + mrow + c_off + hkb);
                ldsm4(c + 4, cLb + mrow + 16 * ASTR * 4 + c_off + hkb);
                #pragma unroll
                for (int gg = 0; gg < 4; gg++) {
                    mma_bf16(accS[mh][gg], aSh, c[2*gg], c[2*gg+1]);
                    mma_bf16(accF[mh][gg], aFh, c[2*gg], c[2*gg+1]);
                }
            }
        }
    }

    // ---- epilogue: hybrid exp (even -> MUFU EX2, odd -> FMA-pipe poly)
    float num = 0.f, den = 0.f;
    #pragma unroll
    for (int mh = 0; mh < 2; mh++)
        #pragma unroll
        for (int gg = 0; gg < 4; gg++)
            #pragma unroll
            for (int r = 0; r < 4; r++) {
                float S = accS[mh][gg][r];
                float e = (r & 1) ? exp_poly(S) : __expf(S);
                den += e;
                num = fmaf(e, accF[mh][gg][r], num);
            }

    // block reduction
    #pragma unroll
    for (int o = 16; o; o >>= 1) {
        num += __shfl_down_sync(0xffffffffu, num, o);
        den += __shfl_down_sync(0xffffffffu, den, o);
    }
    if (lane == 0) { rn[w] = num; rd[w] = den; }
    __syncthreads();
    if (tid == 0) {
        float sn = 0.f, sd = 0.f;
        #pragma unroll
        for (int q = 0; q < 8; q++) { sn += rn[q]; sd += rd[q]; }
        g_pnum[side][b][k][nh * 4 + mq] = sn;
        g_pden[side][b][k][nh * 4 + mq] = sd;
    }
}

// ---------------------------------------------------------------------------
// Finalize: loss = mean_b relu(score_n - score_p + margin).
// ---------------------------------------------------------------------------
__global__ void finalize_kernel(float* __restrict__ out) {
    const int b = threadIdx.x;  // 32 threads
    float sp = 0.f, sn = 0.f;
    #pragma unroll
    for (int k = 0; k < K_; k++) {
        float n0 = 0.f, d0 = 0.f, n1 = 0.f, d1 = 0.f;
        #pragma unroll
        for (int q = 0; q < 8; q++) {
            n0 += g_pnum[0][b][k][q]; d0 += g_pden[0][b][k][q];
            n1 += g_pnum[1][b][k][q]; d1 += g_pden[1][b][k][q];
        }
        sp += n0 / d0;
        sn += n1 / d1;
    }
    float v = fmaxf(sn - sp + 0.2f, 0.f);
    #pragma unroll
    for (int o = 16; o; o >>= 1) v += __shfl_down_sync(0xffffffffu, v, o);
    if (b == 0) out[0] = v * (1.0f / B_);
}

// ---------------------------------------------------------------------------
extern "C" void kernel_launch(void* const* d_in, const int* in_sizes, int n_in,
                              void* d_out, int out_size) {
    const float* he_anchor = (const float*)d_in[0];
    const float* he_pos    = (const float*)d_in[1];
    const float* he_neg    = (const float*)d_in[2];
    const float* W_a2h     = (const float*)d_in[3];
    const float* b_a2h     = (const float*)d_in[4];
    const float* W_c2h     = (const float*)d_in[5];
    const float* b_c2h     = (const float*)d_in[6];
    const float* W_att     = (const float*)d_in[7];
    // d_in[8] = b_att : cancels in softmax
    const float* W_fc      = (const float*)d_in[9];
    // d_in[10] = b_fc : cancels in score difference

    proj_kernel<<<dim3(4, 4, 96), 256>>>(he_anchor, he_pos, he_neg,
                                         W_a2h, b_a2h, W_c2h, b_c2h);

    score_kernel<<<dim3(64, B_, 2), 256>>>(W_att, W_fc);

    finalize_kernel<<<1, 32>>>((float*)d_out);
}

// round 9
// speedup vs baseline: 1.8918x; 1.2356x over previous
#include <cuda_runtime.h>
#include <cuda_bf16.h>
#include <cstdint>

// HGAN triplet loss:
//   score[b] = b_fc + sum_k num_k/den_k       (b_att cancels in softmax,
//   num_k = sum_{n,m} exp(S_k[n,m])*F_k[n,m],  b_fc cancels in score diff)
//   S_k[n,m] = sum_h W_att[k,h]*Aa[h,n]*Ac[h,m]
//   F_k[n,m] = sum_h W_fc [k,h]*Aa[h,n]*Ac[h,m]
// Both the projections AND the score bilinear forms run on HMMA
// (mma.sync m16n8k16 bf16, fp32 acc) with 3-pass hi/lo bf16 splitting.

#define B_ 32
#define N_ 256
#define E_ 300
#define H_ 256
#define K_ 8
#define KSTEPS 19     // ceil(300/16)

// ---------------------------------------------------------------------------
// Device scratch (allocation-free per harness rules)
// ---------------------------------------------------------------------------
__device__ float    g_projT[B_][N_][H_];             // anchor proj, [n][h]
__device__ uint32_t g_Cpk[B_][2][2][256][128];       // [b][side][hi/lo][m][h/2]
__device__ uint32_t g_Wpk[2][2][KSTEPS][256][8];     // [a2h/c2h][hi/lo][ks][h][k/2]
__device__ float    g_pnum[2][B_][K_][8];
__device__ float    g_pden[2][B_][K_][8];

// ---------------------------------------------------------------------------
// Helpers
// ---------------------------------------------------------------------------
__device__ __forceinline__ uint32_t smem_u32(const void* p) {
    uint32_t a;
    asm("{ .reg .u64 t; cvta.to.shared.u64 t, %1; cvt.u32.u64 %0, t; }" : "=r"(a) : "l"(p));
    return a;
}
// pack (v0 -> low half, v1 -> high half) as bf16x2
__device__ __forceinline__ uint32_t cvt2(float v0, float v1) {
    uint32_t r;
    asm("cvt.rn.bf16x2.f32 %0, %1, %2;" : "=r"(r) : "f"(v1), "f"(v0));
    return r;
}
// hi/lo bf16 split of a pair of fp32 values
__device__ __forceinline__ void split2(float v0, float v1, uint32_t& uhi, uint32_t& ulo) {
    uhi = cvt2(v0, v1);
    float f0 = __uint_as_float(uhi << 16);
    float f1 = __uint_as_float(uhi & 0xffff0000u);
    ulo = cvt2(v0 - f0, v1 - f1);
}
__device__ __forceinline__ void ldsm4(uint32_t* r, uint32_t addr) {
    asm volatile("ldmatrix.sync.aligned.m8n8.x4.shared.b16 {%0,%1,%2,%3}, [%4];"
        : "=r"(r[0]), "=r"(r[1]), "=r"(r[2]), "=r"(r[3]) : "r"(addr));
}
__device__ __forceinline__ void mma_bf16(float* d, const uint32_t* a,
                                         uint32_t b0, uint32_t b1) {
    asm volatile("mma.sync.aligned.m16n8k16.row.col.f32.bf16.bf16.f32 "
        "{%0,%1,%2,%3}, {%4,%5,%6,%7}, {%8,%9}, {%0,%1,%2,%3};"
        : "+f"(d[0]), "+f"(d[1]), "+f"(d[2]), "+f"(d[3])
        : "r"(a[0]), "r"(a[1]), "r"(a[2]), "r"(a[3]), "r"(b0), "r"(b1));
}
// exp via 2^(x*log2e), deg-5 minimax poly (rel err ~3e-8), FMA-pipe only.
__device__ __forceinline__ float exp_poly(float x) {
    float t = x * 1.4426950408889634f;
    float fi = rintf(t);
    float f = t - fi;
    float p = 0.00133335581f;
    p = fmaf(p, f, 0.00961804886f);
    p = fmaf(p, f, 0.0555041087f);
    p = fmaf(p, f, 0.240226507f);
    p = fmaf(p, f, 0.69314718056f);
    p = fmaf(p, f, 1.0f);
    float s = __int_as_float(((int)fi + 127) << 23);
    return p * s;
}

// ---------------------------------------------------------------------------
// W prep: hi/lo bf16 split of both weight matrices into k16-step pack.
// grid = 2*KSTEPS blocks x 256 threads; thread = one h row.
// ---------------------------------------------------------------------------
__global__ __launch_bounds__(256)
void wprep_kernel(const float* __restrict__ Wa, const float* __restrict__ Wc) {
    const int mode = blockIdx.x & 1, ks = blockIdx.x >> 1;
    const int h = threadIdx.x;
    const float* W = mode ? Wc : Wa;
    const int e0 = ks * 16;
    float v[16];
    #pragma unroll
    for (int j = 0; j < 16; j++)
        v[j] = (e0 + j < E_) ? W[h * E_ + e0 + j] : 0.f;
    #pragma unroll
    for (int i = 0; i < 8; i++) {
        uint32_t hi, lo;
        split2(v[2 * i], v[2 * i + 1], hi, lo);
        g_Wpk[mode][0][ks][h][i] = hi;
        g_Wpk[mode][1][ks][h][i] = lo;
    }
}

// ---------------------------------------------------------------------------
// Projection on HMMA. CTA = 64n x 256h of one (mode, b); grid (4, 1, 96).
// Warp w: n rows [nq*64 + 16*(w&3), +16), h cols [128*(w>>2), +128).
// K = e streamed in 19 steps of 16 (zero-padded tail). X staged+split into
// smem per kstep; W copied from the pre-split global pack. 3-pass split MMA.
// Epilogue: mode 0 -> fp32 g_projT; mode 1/2 -> hi/lo C-pack.
// ---------------------------------------------------------------------------
#define PSTR 12   // u32 row stride in stage (48B: 16 bf16 + pad, 32-bank perfect)

__global__ __launch_bounds__(256, 2)
void projmma_kernel(const float* __restrict__ Xa, const float* __restrict__ Xp,
                    const float* __restrict__ Xn,
                    const float* __restrict__ ba, const float* __restrict__ bc) {
    __shared__ uint32_t XH[64 * PSTR], XL[64 * PSTR];
    __shared__ uint32_t WH[256 * PSTR], WL[256 * PSTR];
    __shared__ float bias_s[256];

    const int tid = threadIdx.x, lane = tid & 31, w = tid >> 5;
    const int nq = blockIdx.x;
    const int mb = blockIdx.z;            // mode*32 + b
    const int mode = mb >> 5, b = mb & 31;

    const float* X    = (mode == 0) ? Xa : (mode == 1 ? Xp : Xn);
    const float* bias = (mode == 0) ? ba : bc;
    const int    wsel = (mode == 0) ? 0 : 1;

    bias_s[tid] = bias[tid];

    const float* Xbase = X + ((size_t)b * N_ + nq * 64) * E_;
    const int warp_n = w & 3, warp_h = w >> 2;

    const uint32_t xhb = smem_u32(XH), xlb = smem_u32(XL);
    const uint32_t whb = smem_u32(WH), wlb = smem_u32(WL);

    // ldsm address patterns (proven in score kernel; stride 48B here)
    const uint32_t a_off = (uint32_t)(warp_n * 16 + (lane & 15)) * 48 + ((lane >> 4) << 4);
    const uint32_t c_off = (uint32_t)((lane & 7) + ((lane >> 4) << 3)) * 48
                         + (((lane >> 3) & 1) << 4);

    // X fill indices: thread -> (n = tid/4, q = tid%4) float4 of 4 e-values
    const int fx_n = tid >> 2, fx_q = tid & 3;

    float acc[16][4];
    #pragma unroll
    for (int i = 0; i < 16; i++)
        #pragma unroll
        for (int j = 0; j < 4; j++) acc[i][j] = 0.f;

    for (int ks = 0; ks < KSTEPS; ks++) {
        const int e0 = ks * 16;
        __syncthreads();   // previous kstep's ldsm reads done

        // ---- X stage: 64n x 16e fp32 -> split -> XH/XL
        {
            float4 v = make_float4(0.f, 0.f, 0.f, 0.f);
            if (e0 + fx_q * 4 < E_)
                v = *(const float4*)(Xbase + fx_n * E_ + e0 + fx_q * 4);
            uint32_t h0, l0, h1, l1;
            split2(v.x, v.y, h0, l0);
            split2(v.z, v.w, h1, l1);
            const int o = fx_n * PSTR + fx_q * 2;
            XH[o] = h0; XH[o + 1] = h1;
            XL[o] = l0; XL[o + 1] = l1;
        }
        // ---- W stage: copy pre-split pack (4 uint4 per thread)
        #pragma unroll
        for (int i = 0; i < 4; i++) {
            int idx = tid + i * 256;           // 0..1023
            int var = idx >> 9, rem = idx & 511;
            int h = rem >> 1, half = rem & 1;
            uint4 v = *(const uint4*)&g_Wpk[wsel][var][ks][h][half * 4];
            uint32_t* dst = (var ? WL : WH) + h * PSTR + half * 4;
            *(uint4*)dst = v;
        }
        __syncthreads();

        uint32_t aH[4], aL[4];
        ldsm4(aH, xhb + a_off);
        ldsm4(aL, xlb + a_off);
        #pragma unroll
        for (int qh = 0; qh < 4; qh++) {
            const uint32_t hb = (uint32_t)(warp_h * 128 + qh * 32) * 48;
            uint32_t bh[8], bl[8];
            ldsm4(bh + 0, whb + hb + c_off);
            ldsm4(bh + 4, whb + hb + 16 * 48 + c_off);
            ldsm4(bl + 0, wlb + hb + c_off);
            ldsm4(bl + 4, wlb + hb + 16 * 48 + c_off);
            #pragma unroll
            for (int t2 = 0; t2 < 4; t2++) {
                const int ht = qh * 4 + t2;
                mma_bf16(acc[ht], aH, bh[2 * t2], bh[2 * t2 + 1]);
                mma_bf16(acc[ht], aL, bh[2 * t2], bh[2 * t2 + 1]);
                mma_bf16(acc[ht], aH, bl[2 * t2], bl[2 * t2 + 1]);
            }
        }
    }

    // ---- epilogue: bias add, then store fp32 (anchor) or split pack (pos/neg)
    const int g = lane >> 2, q = lane & 3;
    const int n0 = nq * 64 + warp_n * 16 + g;
    #pragma unroll
    for (int ht = 0; ht < 16; ht++) {
        const int h = warp_h * 128 + ht * 8 + 2 * q;
        const float b0 = bias_s[h], b1 = bias_s[h + 1];
        const float x0 = acc[ht][0] + b0, x1 = acc[ht][1] + b1;
        const float x2 = acc[ht][2] + b0, x3 = acc[ht][3] + b1;
        if (mode == 0) {
            *(float2*)&g_projT[b][n0][h]     = make_float2(x0, x1);
            *(float2*)&g_projT[b][n0 + 8][h] = make_float2(x2, x3);
        } else {
            const int side = mode - 1;
            uint32_t hi, lo;
            split2(x0, x1, hi, lo);
            g_Cpk[b][side][0][n0][h >> 1] = hi;
            g_Cpk[b][side][1][n0][h >> 1] = lo;
            split2(x2, x3, hi, lo);
            g_Cpk[b][side][0][n0 + 8][h >> 1] = hi;
            g_Cpk[b][side][1][n0 + 8][h >> 1] = lo;
        }
    }
}

// ---------------------------------------------------------------------------
// Score: CTA = 128n x 64m slice of one (k, b, side). bx = k + 8*mq + 32*nh.
// A fragments built in registers (LDG fp32 -> scale -> hi/lo split);
// C fragments from smem via ldmatrix (pre-split global pack). (unchanged R8)
// ---------------------------------------------------------------------------
#define ASTR 20   // u32 stride per smem row (40 bf16 = 80 B, conflict-free)

__global__ __launch_bounds__(256, 2)
void score_kernel(const float* __restrict__ W_att, const float* __restrict__ W_fc) {
    __shared__ float watt_s[H_], wfc_s[H_];
    __shared__ uint32_t Chi[64 * ASTR], Clo[64 * ASTR];
    __shared__ float rn[8], rd[8];

    const int tid  = threadIdx.x;
    const int lane = tid & 31, w = tid >> 5;
    const int k  = blockIdx.x & 7;
    const int mq = (blockIdx.x >> 3) & 3;
    const int nh = blockIdx.x >> 5;
    const int b = blockIdx.y, side = blockIdx.z;

    for (int h = tid; h < H_; h += 256) {
        watt_s[h] = W_att[k * H_ + h];
        wfc_s[h]  = W_fc [k * H_ + h];
    }

    const float*    At = &g_projT[b][0][0];
    const uint32_t* Cp = &g_Cpk[b][side][0][0][0];
    const uint32_t cHb = smem_u32(Chi), cLb = smem_u32(Clo);

    const int g = lane >> 2, t = lane & 3;
    const int n_r0 = nh * 128 + 16 * w + g;
    const int n_r1 = n_r0 + 8;
    const uint32_t c_row = (lane & 7) + ((lane >> 4) << 3);
    const uint32_t c_off = c_row * ASTR * 4 + (((lane >> 3) & 1) << 4);

    float accS[2][4][4], accF[2][4][4];
    #pragma unroll
    for (int mh = 0; mh < 2; mh++)
        #pragma unroll
        for (int gg = 0; gg < 4; gg++)
            #pragma unroll
            for (int r = 0; r < 4; r++) { accS[mh][gg][r] = 0.f; accF[mh][gg][r] = 0.f; }

    for (int hc = 0; hc < 8; hc++) {
        const int h0 = hc * 32;
        __syncthreads();

        // ---- C fill: 64m x 32h, hi+lo = 4096 u32 -> 2 uint4 per thread
        #pragma unroll
        for (int i = 0; i < 2; i++) {
            int idx = tid + i * 256;
            int var = idx >> 8;
            int rem = idx & 255;
            int m = rem >> 2, q = rem & 3;
            uint4 v = *(const uint4*)(Cp + (size_t)var * 256 * 128
                                        + (size_t)(mq * 64 + m) * 128 + hc * 16 + q * 4);
            uint32_t* dst = (var ? Clo : Chi) + m * ASTR + q * 4;
            *(uint4*)dst = v;
        }
        __syncthreads();

        #pragma unroll
        for (int ks = 0; ks < 2; ks++) {
            const int h0k = h0 + ks * 16;
            float2 v00 = *(const float2*)(At + n_r0 * H_ + h0k + 2 * t);
            float2 v10 = *(const float2*)(At + n_r1 * H_ + h0k + 2 * t);
            float2 v01 = *(const float2*)(At + n_r0 * H_ + h0k + 2 * t + 8);
            float2 v11 = *(const float2*)(At + n_r1 * H_ + h0k + 2 * t + 8);
            float2 wa0 = *(const float2*)(watt_s + h0k + 2 * t);
            float2 wa1 = *(const float2*)(watt_s + h0k + 2 * t + 8);
            float2 wf0 = *(const float2*)(wfc_s  + h0k + 2 * t);
            float2 wf1 = *(const float2*)(wfc_s  + h0k + 2 * t + 8);

            uint32_t aSh[4], aSl[4], aFh[4], aFl[4];
            split2(wa0.x * v00.x, wa0.y * v00.y, aSh[0], aSl[0]);
            split2(wa0.x * v10.x, wa0.y * v10.y, aSh[1], aSl[1]);
            split2(wa1.x * v01.x, wa1.y * v01.y, aSh[2], aSl[2]);
            split2(wa1.x * v11.x, wa1.y * v11.y, aSh[3], aSl[3]);
            split2(wf0.x * v00.x, wf0.y * v00.y, aFh[0], aFl[0]);
            split2(wf0.x * v10.x, wf0.y * v10.y, aFh[1], aFl[1]);
            split2(wf1.x * v01.x, wf1.y * v01.y, aFh[2], aFl[2]);
            split2(wf1.x * v11.x, wf1.y * v11.y, aFh[3], aFl[3]);

            const uint32_t hkb = (uint32_t)(ks * 32);
            #pragma unroll
            for (int mh = 0; mh < 2; mh++) {
                const uint32_t mrow = (uint32_t)(mh * 32) * ASTR * 4;
                uint32_t c[8];
                ldsm4(c + 0, cHb + mrow + c_off + hkb);
                ldsm4(c + 4, cHb + mrow + 16 * ASTR * 4 + c_off + hkb);
                #pragma unroll
                for (int gg = 0; gg < 4; gg++) {
                    mma_bf16(accS[mh][gg], aSh, c[2*gg], c[2*gg+1]);
                    mma_bf16(accS[mh][gg], aSl, c[2*gg], c[2*gg+1]);
                    mma_bf16(accF[mh][gg], aFh, c[2*gg], c[2*gg+1]);
                    mma_bf16(accF[mh][gg], aFl, c[2*gg], c[2*gg+1]);
                }
                ldsm4(c + 0, cLb + mrow + c_off + hkb);
                ldsm4(c + 4, cLb + mrow + 16 * ASTR * 4 + c_off + hkb);
                #pragma unroll
                for (int gg = 0; gg < 4; gg++) {
                    mma_bf16(accS[mh][gg], aSh, c[2*gg], c[2*gg+1]);
                    mma_bf16(accF[mh][gg], aFh, c[2*gg], c[2*gg+1]);
                }
            }
        }
    }

    // ---- epilogue: hybrid exp (even -> MUFU EX2, odd -> FMA-pipe poly)
    float num = 0.f, den = 0.f;
    #pragma unroll
    for (int mh = 0; mh < 2; mh++)
        #pragma unroll
        for (int gg = 0; gg < 4; gg++)
            #pragma unroll
            for (int r = 0; r < 4; r++) {
                float S = accS[mh][gg][r];
                float e = (r & 1) ? exp_poly(S) : __expf(S);
                den += e;
                num = fmaf(e, accF[mh][gg][r], num);
            }

    #pragma unroll
    for (int o = 16; o; o >>= 1) {
        num += __shfl_down_sync(0xffffffffu, num, o);
        den += __shfl_down_sync(0xffffffffu, den, o);
    }
    if (lane == 0) { rn[w] = num; rd[w] = den; }
    __syncthreads();
    if (tid == 0) {
        float sn = 0.f, sd = 0.f;
        #pragma unroll
        for (int q = 0; q < 8; q++) { sn += rn[q]; sd += rd[q]; }
        g_pnum[side][b][k][nh * 4 + mq] = sn;
        g_pden[side][b][k][nh * 4 + mq] = sd;
    }
}

// ---------------------------------------------------------------------------
// Finalize: loss = mean_b relu(score_n - score_p + margin).
// ---------------------------------------------------------------------------
__global__ void finalize_kernel(float* __restrict__ out) {
    const int b = threadIdx.x;  // 32 threads
    float sp = 0.f, sn = 0.f;
    #pragma unroll
    for (int k = 0; k < K_; k++) {
        float n0 = 0.f, d0 = 0.f, n1 = 0.f, d1 = 0.f;
        #pragma unroll
        for (int q = 0; q < 8; q++) {
            n0 += g_pnum[0][b][k][q]; d0 += g_pden[0][b][k][q];
            n1 += g_pnum[1][b][k][q]; d1 += g_pden[1][b][k][q];
        }
        sp += n0 / d0;
        sn += n1 / d1;
    }
    float v = fmaxf(sn - sp + 0.2f, 0.f);
    #pragma unroll
    for (int o = 16; o; o >>= 1) v += __shfl_down_sync(0xffffffffu, v, o);
    if (b == 0) out[0] = v * (1.0f / B_);
}

// ---------------------------------------------------------------------------
extern "C" void kernel_launch(void* const* d_in, const int* in_sizes, int n_in,
                              void* d_out, int out_size) {
    const float* he_anchor = (const float*)d_in[0];
    const float* he_pos    = (const float*)d_in[1];
    const float* he_neg    = (const float*)d_in[2];
    const float* W_a2h     = (const float*)d_in[3];
    const float* b_a2h     = (const float*)d_in[4];
    const float* W_c2h     = (const float*)d_in[5];
    const float* b_c2h     = (const float*)d_in[6];
    const float* W_att     = (const float*)d_in[7];
    // d_in[8] = b_att : cancels in softmax
    const float* W_fc      = (const float*)d_in[9];
    // d_in[10] = b_fc : cancels in score difference

    wprep_kernel<<<2 * KSTEPS, 256>>>(W_a2h, W_c2h);

    projmma_kernel<<<dim3(4, 1, 96), 256>>>(he_anchor, he_pos, he_neg,
                                            b_a2h, b_c2h);

    score_kernel<<<dim3(64, B_, 2), 256>>>(W_att, W_fc);

    finalize_kernel<<<1, 32>>>((float*)d_out);
}